// round 16
// baseline (speedup 1.0000x reference)
#include <cuda_runtime.h>
#include <cstddef>

// BinaryMaskEdgeSmoothing — exact integer-combinatorics reduction (validated,
// rel_err=0.0):
//   S9 = 3x3 sum, edges = 9*c - S9, n = Gauss numerator = S9 + m3 + vcen
//   out = (n + (|edges| < 5.5 ? c : 0)) > 8.5
// R16 == R15 resubmission (R15 never ran: broker GPUAcquisitionTimeout).
// Committed R14 body (row-pair, MLP_p1=2, __stcs; 85.8us) +
// __launch_bounds__(256, 6): reg budget 42 (was 48 natural) -> 6 CTAs/SM.
// Mild 12.5% clamp; the 2-row prefetch batch is structurally live, so the
// shave must come from decide-block temporaries, not the load schedule.

#define Wd 1024
#define Hd 1024
#define RPT 16   // output rows per thread (8 iterations x 2 rows)

__device__ __forceinline__ void load_row(const float* __restrict__ base, int r,
                                         int j, float v[6]) {
    if ((unsigned)r >= (unsigned)Hd) {            // SAME zero padding
        v[0] = v[1] = v[2] = v[3] = v[4] = v[5] = 0.f;
        return;
    }
    const float* p = base + (size_t)r * Wd + (j << 2);
    float4 cc = __ldg((const float4*)p);
    v[0] = (j > 0) ? __ldg(p - 1) : 0.f;          // left halo (L1-hit)
    v[1] = cc.x; v[2] = cc.y; v[3] = cc.z; v[4] = cc.w;
    v[5] = (j < (Wd / 4 - 1)) ? __ldg(p + 4) : 0.f;  // right halo (L1-hit)
}

// Decision for one output row given its 3-row column sums cs[6] and middle row m[6].
__device__ __forceinline__ void decide4(const float cs[6], const float m[6],
                                        float res[4]) {
    #pragma unroll
    for (int i = 0; i < 4; ++i) {
        float S9    = cs[i] + cs[i + 1] + cs[i + 2];
        float m3    = m[i]  + m[i + 1]  + m[i + 2];
        float cv    = m[i + 1];
        float vcen  = cs[i + 1] + cv;             // t_c + 2*m_c + b_c
        float nG    = S9 + m3 + vcen;             // Gauss numerator, 0..16
        float edges = fmaf(9.f, cv, -S9);         // Laplacian response, -9..9
        float bonus = (fabsf(edges) < 5.5f) ? cv : 0.f;
        res[i] = (nG + bonus > 8.5f) ? 1.f : 0.f;
    }
}

__global__ void __launch_bounds__(256, 6)
mask_smooth_kernel(const float* __restrict__ in, float* __restrict__ out) {
    const int img = blockIdx.y;
    const int r0  = blockIdx.x * RPT;
    const int j   = threadIdx.x;                  // float4 column index 0..255

    const float* base = in  + (size_t)img * Hd * Wd;
    float*       ob   = out + (size_t)img * Hd * Wd;

    // Rolling window rows r-1..r+2 plus two prefetch buffers.
    float a[6], b[6], c[6], d[6], n1[6], n2[6];
    load_row(base, r0 - 1, j, a);
    load_row(base, r0,     j, b);
    load_row(base, r0 + 1, j, c);
    load_row(base, r0 + 2, j, d);

    #pragma unroll
    for (int it = 0; it < RPT / 2; ++it) {
        const int r = r0 + 2 * it;

        // Front-batched prefetch of the next pair's rows (2 independent
        // LDG.128 -> MLP_p1 = 2). Compile-time skipped on the last iteration.
        if (it < RPT / 2 - 1) {
            load_row(base, r + 3, j, n1);
            load_row(base, r + 4, j, n2);
        }

        float bc[6], cs0[6], cs1[6];
        #pragma unroll
        for (int k = 0; k < 6; ++k) {
            bc[k]  = b[k] + c[k];                 // shared by both output rows
            cs0[k] = a[k] + bc[k];                // rows r-1,r,r+1
            cs1[k] = bc[k] + d[k];                // rows r,r+1,r+2
        }

        float res0[4], res1[4];
        decide4(cs0, b, res0);                    // output row r   (middle = b)
        decide4(cs1, c, res1);                    // output row r+1 (middle = c)

        float4 o0, o1;
        o0.x = res0[0]; o0.y = res0[1]; o0.z = res0[2]; o0.w = res0[3];
        o1.x = res1[0]; o1.y = res1[1]; o1.z = res1[2]; o1.w = res1[3];
        __stcs((float4*)(ob + (size_t)r       * Wd + (j << 2)), o0);
        __stcs((float4*)(ob + (size_t)(r + 1) * Wd + (j << 2)), o1);

        #pragma unroll
        for (int k = 0; k < 6; ++k) {             // roll window by 2 rows
            a[k] = c[k]; b[k] = d[k]; c[k] = n1[k]; d[k] = n2[k];
        }
    }
}

extern "C" void kernel_launch(void* const* d_in, const int* in_sizes, int n_in,
                              void* d_out, int out_size) {
    const float* mask = (const float*)d_in[0];    // [B*C, H, W] fp32 binary
    float*       outp = (float*)d_out;
    const int nimg = in_sizes[0] / (Hd * Wd);     // 64 for the reference shapes

    dim3 grid(Hd / RPT, nimg);
    mask_smooth_kernel<<<grid, 256>>>(mask, outp);
}